// round 3
// baseline (speedup 1.0000x reference)
#include <cuda_runtime.h>
#include <cuda_bf16.h>

// ---------------------------------------------------------------------------
// MLP_TI_Gram: y = MLP(mean-of-shifted-diagonal of per-batch Gram matrix)
// diag-mean == circular autocorrelation over sequence dim (3 channels)/N,
// with symmetry c[r] == c[N-r].  B=128, N=1024, H=128.
// Pipeline: corr -> split-K gemm1 (partials) -> reduce + celu + mlp2/3.
// ---------------------------------------------------------------------------

#define BATCH 128
#define NSEQ  1024
#define HID   128
#define KSPLIT 128            // gemm1 K-chunks (8 j's each)

typedef unsigned long long u64;

__device__ float g_c[BATCH * NSEQ];                 // correlation (scratch)
__device__ u64   g_part[64 * KSPLIT * HID];         // packed batch-pair partials (8MB)

// ---- f32x2 packed helpers (Blackwell, PTX-only) ---------------------------
__device__ __forceinline__ u64 pk2(float lo, float hi) {
    u64 r;
    asm("mov.b64 %0, {%1,%2};" : "=l"(r) : "f"(lo), "f"(hi));
    return r;
}
__device__ __forceinline__ void upk2(u64 v, float& lo, float& hi) {
    asm("mov.b64 {%0,%1}, %2;" : "=f"(lo), "=f"(hi) : "l"(v));
}
__device__ __forceinline__ u64 fma2(u64 a, u64 b, u64 c) {
    u64 d;
    asm("fma.rn.f32x2 %0, %1, %2, %3;" : "=l"(d) : "l"(a), "l"(b), "l"(c));
    return d;
}
__device__ __forceinline__ u64 add2(u64 a, u64 b) {
    u64 d;
    asm("add.rn.f32x2 %0, %1, %2;" : "=l"(d) : "l"(a), "l"(b));
    return d;
}

__device__ __forceinline__ int pbase(int i) { return i + (i >> 3); }

__device__ __forceinline__ float celu1(float v) {
    return v > 0.0f ? v : expm1f(v);
}

// ---------------------------------------------------------------------------
// Kernel 1: circular autocorrelation with symmetry (at fma2-issue floor).
// 128 blocks (one per batch), 512 threads.
// ---------------------------------------------------------------------------
__global__ __launch_bounds__(512, 1)
void corr_kernel(const float* __restrict__ x) {
    __shared__ u64 xs01[1736];   // (x0,x1) pairs, i in [0,1536), padded
    __shared__ u64 xs2ab[1160];  // (x2[i], x2[i+512 mod N]), i in [0,1024)
    __shared__ float red[8][512];

    const int b = blockIdx.x;
    const int t = threadIdx.x;
    const float* __restrict__ xb = x + b * NSEQ * 3;

    for (int i = t; i < 1536; i += 512) {
        int j = i & (NSEQ - 1);
        xs01[pbase(i)] = pk2(xb[j * 3 + 0], xb[j * 3 + 1]);
    }
    for (int i = t; i < 1024; i += 512) {
        xs2ab[pbase(i)] = pk2(xb[i * 3 + 2], xb[((i + 512) & (NSEQ - 1)) * 3 + 2]);
    }
    __syncthreads();

    const int g  = t & 63;
    const int s  = t >> 6;
    const int r0 = g << 3;
    const int mA = s << 6;

    u64 w01a[8], w01b[8], w2[8];
    u64 acc01[8], acc2[8];
#pragma unroll
    for (int k = 0; k < 8; k++) { acc01[k] = 0ull; acc2[k] = 0ull; }

    {
        int bA = pbase(mA + r0);
        int bB = pbase(mA + 512 + r0);
#pragma unroll
        for (int k = 0; k < 8; k++) {
            w01a[k] = xs01[bA + k];
            w01b[k] = xs01[bB + k];
            w2[k]   = xs2ab[bA + k];
        }
    }

#pragma unroll 1
    for (int m = mA; m < mA + 64; m += 8) {
        const int baseA  = pbase(m);
        const int baseB  = pbase(m + 512);
        const int rbaseA = pbase(m + r0 + 8);
        const int rbaseB = pbase(m + 512 + r0 + 8);
#pragma unroll
        for (int u = 0; u < 8; u++) {
            u64 a01a = xs01[baseA + u];
            u64 a01b = xs01[baseB + u];
            u64 a2   = xs2ab[baseA + u];
#pragma unroll
            for (int k = 0; k < 8; k++) {
                int idx = (u + k) & 7;
                acc01[k] = fma2(a01a, w01a[idx], acc01[k]);
                acc01[k] = fma2(a01b, w01b[idx], acc01[k]);
                acc2[k]  = fma2(a2,   w2[idx],   acc2[k]);
            }
            w01a[u] = xs01[rbaseA + u];
            w01b[u] = xs01[rbaseB + u];
            w2[u]   = xs2ab[rbaseA + u];
        }
    }

#pragma unroll
    for (int k = 0; k < 8; k++) {
        float ax, ay, cx, cy;
        upk2(acc01[k], ax, ay);
        upk2(acc2[k],  cx, cy);
        red[s][r0 + k] = ax + ay + cx + cy;
    }
    __syncthreads();

    const float inv = 1.0f / (float)NSEQ;
    if (t < 512) {
        int r = t;
        float v = (red[0][r] + red[1][r] + red[2][r] + red[3][r] +
                   red[4][r] + red[5][r] + red[6][r] + red[7][r]) * inv;
        g_c[b * NSEQ + r] = v;
        if (r > 0) g_c[b * NSEQ + (NSEQ - r)] = v;
    }

    if (t < 32) {  // r = 512 self-mirror
        float sum = 0.0f;
        for (int j = t; j < 512; j += 32) {
            float p0x, p0y, q0x, q0y, cx, cy;
            upk2(xs01[pbase(j)], p0x, p0y);
            upk2(xs01[pbase(j + 512)], q0x, q0y);
            upk2(xs2ab[pbase(j)], cx, cy);
            sum += p0x * q0x + p0y * q0y + cx * cy;
        }
        sum *= 2.0f;
#pragma unroll
        for (int o = 16; o > 0; o >>= 1) sum += __shfl_down_sync(0xffffffffu, sum, o);
        if (t == 0) g_c[b * NSEQ + 512] = sum * inv;
    }
}

// ---------------------------------------------------------------------------
// Kernel 2: split-K layer-1 GEMM partials.
// 128 blocks; block kc handles j in [8kc, 8kc+8) for ALL batches.
// W1 read once chip-wide. Batches packed in f32x2 pairs.
// Thread t: bp = t>>3 (batch pair), q = t&7 (16-h chunk).
// ---------------------------------------------------------------------------
__global__ __launch_bounds__(512, 1)
void gemm1_kernel(const float* __restrict__ W1) {
    __shared__ float cs[8][132];      // c[j][b], padded vs bank conflicts
    __shared__ u64   w1d[8][HID];     // W1 duplicated into both f32x2 lanes

    const int kc = blockIdx.x;
    const int t  = threadIdx.x;
    const int j0 = kc * 8;

    {   // stage c chunk (transpose b-major -> j rows)
        int jj = t & 7, b = t >> 3;   // b in [0,64)
        cs[jj][b]      = g_c[b * NSEQ + j0 + jj];
        cs[jj][b + 64] = g_c[(b + 64) * NSEQ + j0 + jj];
    }
    {   // stage W1 chunk, lane-duplicated
        int h = t & 127, j = t >> 7;  // j in [0,4)
        float wa = W1[(j0 + j) * HID + h];
        float wb = W1[(j0 + j + 4) * HID + h];
        w1d[j][h]     = pk2(wa, wa);
        w1d[j + 4][h] = pk2(wb, wb);
    }
    __syncthreads();

    const int bp = t >> 3;
    const int q  = t & 7;
    const int h0 = q * 16;

    u64 acc[16];
#pragma unroll
    for (int i = 0; i < 16; i++) acc[i] = 0ull;

#pragma unroll
    for (int j = 0; j < 8; j++) {
        u64 a = *(const u64*)&cs[j][bp * 2];
        const ulonglong2* wrow = (const ulonglong2*)&w1d[j][h0];
#pragma unroll
        for (int i = 0; i < 8; i++) {
            ulonglong2 wv = wrow[i];
            acc[2 * i]     = fma2(a, wv.x, acc[2 * i]);
            acc[2 * i + 1] = fma2(a, wv.y, acc[2 * i + 1]);
        }
    }

    u64* dst = g_part + ((size_t)bp * KSPLIT + kc) * HID + h0;
#pragma unroll
    for (int i = 0; i < 8; i++) {
        ((ulonglong2*)dst)[i] = make_ulonglong2(acc[2 * i], acc[2 * i + 1]);
    }
}

// ---------------------------------------------------------------------------
// Kernel 3: reduce partials -> celu -> layer2 -> celu -> layer3.
// 64 blocks (one per batch pair), 512 threads.
// ---------------------------------------------------------------------------
__global__ __launch_bounds__(512, 1)
void mlp23_kernel(const float* __restrict__ b1,
                  const float* __restrict__ W2, const float* __restrict__ b2,
                  const float* __restrict__ W3, const float* __restrict__ b3,
                  float* __restrict__ out) {
    __shared__ u64   red[4][HID];
    __shared__ float h1s[2][HID];
    __shared__ float s2[2][2][HID];
    __shared__ float rbuf[2][HID];

    const int bp = blockIdx.x;
    const int t  = threadIdx.x;
    const int h  = t & 127;

    {   // reduce 128 K-partials (packed pairs), 4 kc-quarters
        int kq = t >> 7;
        const u64* src = g_part + ((size_t)bp * KSPLIT + kq * 32) * HID + h;
        u64 a0 = 0ull, a1 = 0ull, a2 = 0ull, a3 = 0ull;
#pragma unroll
        for (int k = 0; k < 32; k += 4) {
            a0 = add2(a0, src[(k + 0) * HID]);
            a1 = add2(a1, src[(k + 1) * HID]);
            a2 = add2(a2, src[(k + 2) * HID]);
            a3 = add2(a3, src[(k + 3) * HID]);
        }
        red[kq][h] = add2(add2(a0, a1), add2(a2, a3));
    }
    __syncthreads();

    if (t < 128) {
        u64 s = add2(add2(red[0][h], red[1][h]), add2(red[2][h], red[3][h]));
        float va, vb;
        upk2(s, va, vb);
        float bb = b1[h];
        h1s[0][h] = celu1(va + bb);
        h1s[1][h] = celu1(vb + bb);
    }
    __syncthreads();

    {   // layer 2: k split 2-ways, batch split 2-ways
        int g2 = t >> 7;
        int bi = g2 & 1;
        int kh = g2 >> 1;
        const float* h1p = h1s[bi];
        const int k0 = kh * 64;
        float acc0 = 0.f, acc1 = 0.f, acc2f = 0.f, acc3 = 0.f;
#pragma unroll
        for (int k = k0; k < k0 + 64; k += 4) {
            acc0  += h1p[k + 0] * W2[(k + 0) * HID + h];
            acc1  += h1p[k + 1] * W2[(k + 1) * HID + h];
            acc2f += h1p[k + 2] * W2[(k + 2) * HID + h];
            acc3  += h1p[k + 3] * W2[(k + 3) * HID + h];
        }
        s2[kh][bi][h] = (acc0 + acc1) + (acc2f + acc3);
    }
    __syncthreads();

    if (t < 256) {
        int bi = t >> 7;
        float v = s2[0][bi][h] + s2[1][bi][h] + b2[h];
        rbuf[bi][h] = celu1(v) * W3[h];
    }
    __syncthreads();

#pragma unroll
    for (int o = 64; o > 0; o >>= 1) {
        if (t < 2 * o) {
            int bi = t >= o ? 1 : 0;
            int hh = t - bi * o;
            rbuf[bi][hh] += rbuf[bi][hh + o];
        }
        __syncthreads();
    }
    if (t < 2) out[bp * 2 + t] = rbuf[t][0] + b3[0];
}

// ---------------------------------------------------------------------------
extern "C" void kernel_launch(void* const* d_in, const int* in_sizes, int n_in,
                              void* d_out, int out_size) {
    const float* x  = (const float*)d_in[0];
    const float* W1 = (const float*)d_in[1];
    const float* b1 = (const float*)d_in[2];
    const float* W2 = (const float*)d_in[3];
    const float* b2 = (const float*)d_in[4];
    const float* W3 = (const float*)d_in[5];
    const float* b3 = (const float*)d_in[6];
    float* out = (float*)d_out;

    corr_kernel<<<BATCH, 512>>>(x);
    gemm1_kernel<<<KSPLIT, 512>>>(W1);
    mlp23_kernel<<<BATCH / 2, 512>>>(b1, W2, b2, W3, b3, out);
}

// round 4
// speedup vs baseline: 1.7890x; 1.7890x over previous
#include <cuda_runtime.h>
#include <cuda_bf16.h>

// ---------------------------------------------------------------------------
// MLP_TI_Gram: y = MLP(mean-of-shifted-diagonal of per-batch Gram matrix)
// diag-mean == circular autocorrelation over sequence dim (3 channels)/N,
// with symmetry c[r] == c[N-r].  B=128, N=1024, H=128.
// Pipeline: corr -> tiled gemm1 (full-K per block, writes final h1) -> mlp23.
// ---------------------------------------------------------------------------

#define BATCH 128
#define NSEQ  1024
#define HID   128

typedef unsigned long long u64;

__device__ float g_c[BATCH * NSEQ];    // correlation (scratch)
__device__ float g_h1[BATCH * HID];    // layer-1 activations (scratch, 64KB)

// ---- f32x2 packed helpers (Blackwell, PTX-only) ---------------------------
__device__ __forceinline__ u64 pk2(float lo, float hi) {
    u64 r;
    asm("mov.b64 %0, {%1,%2};" : "=l"(r) : "f"(lo), "f"(hi));
    return r;
}
__device__ __forceinline__ void upk2(u64 v, float& lo, float& hi) {
    asm("mov.b64 {%0,%1}, %2;" : "=f"(lo), "=f"(hi) : "l"(v));
}
__device__ __forceinline__ u64 fma2(u64 a, u64 b, u64 c) {
    u64 d;
    asm("fma.rn.f32x2 %0, %1, %2, %3;" : "=l"(d) : "l"(a), "l"(b), "l"(c));
    return d;
}
__device__ __forceinline__ u64 add2(u64 a, u64 b) {
    u64 d;
    asm("add.rn.f32x2 %0, %1, %2;" : "=l"(d) : "l"(a), "l"(b));
    return d;
}

__device__ __forceinline__ int pbase(int i) { return i + (i >> 3); }

__device__ __forceinline__ float celu1(float v) {
    return v > 0.0f ? v : expm1f(v);
}

// ---------------------------------------------------------------------------
// Kernel 1: circular autocorrelation with symmetry.
// 128 blocks (one per batch), 512 threads.
// ---------------------------------------------------------------------------
__global__ __launch_bounds__(512, 1)
void corr_kernel(const float* __restrict__ x) {
    __shared__ u64 xs01[1736];   // (x0,x1) pairs, i in [0,1536), padded
    __shared__ u64 xs2ab[1160];  // (x2[i], x2[i+512 mod N]), i in [0,1024)
    __shared__ float red[8][512];

    const int b = blockIdx.x;
    const int t = threadIdx.x;
    const float* __restrict__ xb = x + b * NSEQ * 3;

    for (int i = t; i < 1536; i += 512) {
        int j = i & (NSEQ - 1);
        xs01[pbase(i)] = pk2(xb[j * 3 + 0], xb[j * 3 + 1]);
    }
    for (int i = t; i < 1024; i += 512) {
        xs2ab[pbase(i)] = pk2(xb[i * 3 + 2], xb[((i + 512) & (NSEQ - 1)) * 3 + 2]);
    }
    __syncthreads();

    const int g  = t & 63;
    const int s  = t >> 6;
    const int r0 = g << 3;
    const int mA = s << 6;

    u64 w01a[8], w01b[8], w2[8];
    u64 acc01[8], acc2[8];
#pragma unroll
    for (int k = 0; k < 8; k++) { acc01[k] = 0ull; acc2[k] = 0ull; }

    {
        int bA = pbase(mA + r0);
        int bB = pbase(mA + 512 + r0);
#pragma unroll
        for (int k = 0; k < 8; k++) {
            w01a[k] = xs01[bA + k];
            w01b[k] = xs01[bB + k];
            w2[k]   = xs2ab[bA + k];
        }
    }

#pragma unroll 1
    for (int m = mA; m < mA + 64; m += 8) {
        const int baseA  = pbase(m);
        const int baseB  = pbase(m + 512);
        const int rbaseA = pbase(m + r0 + 8);
        const int rbaseB = pbase(m + 512 + r0 + 8);
#pragma unroll
        for (int u = 0; u < 8; u++) {
            u64 a01a = xs01[baseA + u];
            u64 a01b = xs01[baseB + u];
            u64 a2   = xs2ab[baseA + u];
#pragma unroll
            for (int k = 0; k < 8; k++) {
                int idx = (u + k) & 7;
                acc01[k] = fma2(a01a, w01a[idx], acc01[k]);
                acc01[k] = fma2(a01b, w01b[idx], acc01[k]);
                acc2[k]  = fma2(a2,   w2[idx],   acc2[k]);
            }
            w01a[u] = xs01[rbaseA + u];
            w01b[u] = xs01[rbaseB + u];
            w2[u]   = xs2ab[rbaseA + u];
        }
    }

#pragma unroll
    for (int k = 0; k < 8; k++) {
        float ax, ay, cx, cy;
        upk2(acc01[k], ax, ay);
        upk2(acc2[k],  cx, cy);
        red[s][r0 + k] = ax + ay + cx + cy;
    }
    __syncthreads();

    const float inv = 1.0f / (float)NSEQ;
    if (t < 512) {
        int r = t;
        float v = (red[0][r] + red[1][r] + red[2][r] + red[3][r] +
                   red[4][r] + red[5][r] + red[6][r] + red[7][r]) * inv;
        g_c[b * NSEQ + r] = v;
        if (r > 0) g_c[b * NSEQ + (NSEQ - r)] = v;
    }

    if (t < 32) {  // r = 512 self-mirror
        float sum = 0.0f;
        for (int j = t; j < 512; j += 32) {
            float p0x, p0y, q0x, q0y, cx, cy;
            upk2(xs01[pbase(j)], p0x, p0y);
            upk2(xs01[pbase(j + 512)], q0x, q0y);
            upk2(xs2ab[pbase(j)], cx, cy);
            sum += p0x * q0x + p0y * q0y + cx * cy;
        }
        sum *= 2.0f;
#pragma unroll
        for (int o = 16; o > 0; o >>= 1) sum += __shfl_down_sync(0xffffffffu, sum, o);
        if (t == 0) g_c[b * NSEQ + 512] = sum * inv;
    }
}

// ---------------------------------------------------------------------------
// Kernel 2: tiled layer-1 GEMM, full K per block, writes FINAL h1 (w/ celu).
// Grid 128 = 16 batch-tiles (8 batches) x 8 h-tiles (16 h). 512 threads.
// Dynamic smem: csh[4][1025] u64 (c packed batch-pairs, padded),
//               w1d[1024][16] u64 (W1 duplicated into both f32x2 lanes),
//               red[32][66]  u64 (per-jq partials, padded).
// Thread t: bp = t&3 (batch pair), h4 = (t>>2)&3 (4-h group), jq = t>>4 (32 j).
// ---------------------------------------------------------------------------
#define CSH_PITCH 1025
#define RED_PITCH 66
#define GEMM1_SMEM ((4 * CSH_PITCH + 1024 * 16 + 32 * RED_PITCH) * 8)

__global__ __launch_bounds__(512, 1)
void gemm1_kernel(const float* __restrict__ W1, const float* __restrict__ b1) {
    extern __shared__ char dsm[];
    u64 (*csh)[CSH_PITCH] = (u64(*)[CSH_PITCH])dsm;
    u64 (*w1d)[16]        = (u64(*)[16])(dsm + 4 * CSH_PITCH * 8);
    u64 (*red)[RED_PITCH] = (u64(*)[RED_PITCH])(dsm + (4 * CSH_PITCH + 1024 * 16) * 8);

    const int t  = threadIdx.x;
    const int bt = blockIdx.x >> 3;
    const int ht = blockIdx.x & 7;
    const int b0 = bt * 8;
    const int H0 = ht * 16;

    // stage c (packed batch pairs): 8 iters, coalesced
#pragma unroll
    for (int it = 0; it < 8; it++) {
        int idx = t + it * 512;           // [0, 4096)
        int bp_ = idx >> 10, j = idx & 1023;
        csh[bp_][j] = pk2(g_c[(b0 + 2 * bp_) * NSEQ + j],
                          g_c[(b0 + 2 * bp_ + 1) * NSEQ + j]);
    }
    // stage W1 slice, lane-duplicated: 8 iters of float4
#pragma unroll
    for (int it = 0; it < 8; it++) {
        int idx = t + it * 512;           // [0, 4096)
        int j = idx >> 2, hq = idx & 3;
        float4 wv = *(const float4*)&W1[j * HID + H0 + hq * 4];
        ulonglong2* dst = (ulonglong2*)&w1d[j][hq * 4];
        dst[0] = make_ulonglong2(pk2(wv.x, wv.x), pk2(wv.y, wv.y));
        dst[1] = make_ulonglong2(pk2(wv.z, wv.z), pk2(wv.w, wv.w));
    }
    __syncthreads();

    const int bp = t & 3;
    const int h4 = (t >> 2) & 3;
    const int jq = t >> 4;                // [0,32)
    const int j0 = jq * 32;

    u64 a0 = 0ull, a1 = 0ull, a2 = 0ull, a3 = 0ull;
#pragma unroll 8
    for (int j = j0; j < j0 + 32; j++) {
        u64 cv = csh[bp][j];
        const ulonglong2* wr = (const ulonglong2*)&w1d[j][h4 * 4];
        ulonglong2 w01 = wr[0];
        ulonglong2 w23 = wr[1];
        a0 = fma2(cv, w01.x, a0);
        a1 = fma2(cv, w01.y, a1);
        a2 = fma2(cv, w23.x, a2);
        a3 = fma2(cv, w23.y, a3);
    }
    {
        ulonglong2* rr = (ulonglong2*)&red[jq][bp * 16 + h4 * 4];
        rr[0] = make_ulonglong2(a0, a1);
        rr[1] = make_ulonglong2(a2, a3);
    }
    __syncthreads();

    if (t < 64) {
        int bp_ = t >> 4, h = t & 15;
        int cell = bp_ * 16 + h;
        u64 s0 = 0ull, s1 = 0ull, s2 = 0ull, s3 = 0ull;
#pragma unroll
        for (int q = 0; q < 32; q += 4) {
            s0 = add2(s0, red[q + 0][cell]);
            s1 = add2(s1, red[q + 1][cell]);
            s2 = add2(s2, red[q + 2][cell]);
            s3 = add2(s3, red[q + 3][cell]);
        }
        u64 s = add2(add2(s0, s1), add2(s2, s3));
        float va, vb;
        upk2(s, va, vb);
        float bb = b1[H0 + h];
        g_h1[(b0 + 2 * bp_) * HID + H0 + h]     = celu1(va + bb);
        g_h1[(b0 + 2 * bp_ + 1) * HID + H0 + h] = celu1(vb + bb);
    }
}

// ---------------------------------------------------------------------------
// Kernel 3: layers 2+3. 128 blocks (one per batch), 256 threads (k split 2).
// ---------------------------------------------------------------------------
__global__ __launch_bounds__(256, 1)
void mlp23_kernel(const float* __restrict__ W2, const float* __restrict__ b2,
                  const float* __restrict__ W3, const float* __restrict__ b3,
                  float* __restrict__ out) {
    __shared__ float h1s[HID];
    __shared__ float s2[2][HID];

    const int b = blockIdx.x, t = threadIdx.x;
    if (t < HID) h1s[t] = g_h1[b * HID + t];
    __syncthreads();

    const int kh = t >> 7, h = t & (HID - 1);
    const int k0 = kh * 64;
    float acc0 = 0.f, acc1 = 0.f, acc2 = 0.f, acc3 = 0.f;
#pragma unroll
    for (int k = k0; k < k0 + 64; k += 4) {
        acc0 += h1s[k + 0] * W2[(k + 0) * HID + h];
        acc1 += h1s[k + 1] * W2[(k + 1) * HID + h];
        acc2 += h1s[k + 2] * W2[(k + 2) * HID + h];
        acc3 += h1s[k + 3] * W2[(k + 3) * HID + h];
    }
    s2[kh][h] = (acc0 + acc1) + (acc2 + acc3);
    __syncthreads();

    if (t < HID) {
        float v = s2[0][t] + s2[1][t] + b2[t];
        s2[0][t] = celu1(v) * W3[t];
    }
    __syncthreads();
#pragma unroll
    for (int o = 64; o > 0; o >>= 1) {
        if (t < o) s2[0][t] += s2[0][t + o];
        __syncthreads();
    }
    if (t == 0) out[b] = s2[0][0] + b3[0];
}

// ---------------------------------------------------------------------------
extern "C" void kernel_launch(void* const* d_in, const int* in_sizes, int n_in,
                              void* d_out, int out_size) {
    const float* x  = (const float*)d_in[0];
    const float* W1 = (const float*)d_in[1];
    const float* b1 = (const float*)d_in[2];
    const float* W2 = (const float*)d_in[3];
    const float* b2 = (const float*)d_in[4];
    const float* W3 = (const float*)d_in[5];
    const float* b3 = (const float*)d_in[6];
    float* out = (float*)d_out;

    cudaFuncSetAttribute(gemm1_kernel,
                         cudaFuncAttributeMaxDynamicSharedMemorySize, GEMM1_SMEM);

    corr_kernel<<<BATCH, 512>>>(x);
    gemm1_kernel<<<128, 512, GEMM1_SMEM>>>(W1, b1);
    mlp23_kernel<<<BATCH, 256>>>(W2, b2, W3, b3, out);
}

// round 5
// speedup vs baseline: 2.1050x; 1.1767x over previous
#include <cuda_runtime.h>
#include <cuda_bf16.h>

// ---------------------------------------------------------------------------
// MLP_TI_Gram: y = MLP(mean-of-shifted-diagonal of per-batch Gram matrix)
// diag-mean == circular autocorrelation == FFT(sum_d |FFT(x_d)|^2)/N^2
// (Wiener-Khinchin; P real-even so inverse == forward FFT, real part).
// B=128, N=1024, H=128.
// Pipeline: fftcorr -> tiled gemm1 (writes final h1) -> mlp23.
// ---------------------------------------------------------------------------

#define BATCH 128
#define NSEQ  1024
#define HID   128

typedef unsigned long long u64;

__device__ float g_c[BATCH * NSEQ];    // correlation (scratch)
__device__ float g_h1[BATCH * HID];    // layer-1 activations (scratch)

// ---- f32x2 packed helpers (Blackwell, PTX-only) ---------------------------
__device__ __forceinline__ u64 pk2(float lo, float hi) {
    u64 r;
    asm("mov.b64 %0, {%1,%2};" : "=l"(r) : "f"(lo), "f"(hi));
    return r;
}
__device__ __forceinline__ void upk2(u64 v, float& lo, float& hi) {
    asm("mov.b64 {%0,%1}, %2;" : "=f"(lo), "=f"(hi) : "l"(v));
}
__device__ __forceinline__ u64 fma2(u64 a, u64 b, u64 c) {
    u64 d;
    asm("fma.rn.f32x2 %0, %1, %2, %3;" : "=l"(d) : "l"(a), "l"(b), "l"(c));
    return d;
}
__device__ __forceinline__ u64 add2(u64 a, u64 b) {
    u64 d;
    asm("add.rn.f32x2 %0, %1, %2;" : "=l"(d) : "l"(a), "l"(b));
    return d;
}

__device__ __forceinline__ float celu1(float v) {
    return v > 0.0f ? v : expm1f(v);
}

// ---------------------------------------------------------------------------
// Kernel 1: correlation via FFT (Wiener-Khinchin).
// 128 blocks (one per batch), 512 threads.
// Forward: 2 complex 1024-pt FFTs (ch0 + i*ch1 packed, ch2 + 0i).
// P[k] = 0.5*(|Z01[k]|^2 + |Z01[N-k]|^2) + |Z2[k]|^2   (covers all 3 channels)
// c[r] = Re(FFT(P))[r] / N^2.
// Stockham autosort radix-2: 10 stages, ping-pong smem, no bit reversal.
// ---------------------------------------------------------------------------
__global__ __launch_bounds__(512, 1)
void fftcorr_kernel(const float* __restrict__ x) {
    __shared__ float2 bufA[2][1024];   // 16KB
    __shared__ float2 bufB[2][1024];   // 16KB
    __shared__ float2 tw[512];         // W_1024^m, m in [0,512)

    const int b = blockIdx.x;
    const int t = threadIdx.x;

    // twiddle table: tw[m] = exp(-2*pi*i*m/1024) = (cos(pi m/512), -sin(pi m/512))
    {
        float s_, c_;
        sincospif(-(float)t * (1.0f / 512.0f), &s_, &c_);
        tw[t] = make_float2(c_, s_);
    }
    // zero imag of channel-2 signal
    bufA[1][t].y = 0.0f;
    bufA[1][t + 512].y = 0.0f;

    // load x[b] : 3072 floats = 768 float4, scatter to (j, d)
    {
        const float4* __restrict__ xv = (const float4*)(x + (size_t)b * NSEQ * 3);
        for (int i = t; i < 768; i += 512) {
            float4 v = xv[i];
            float vals[4] = {v.x, v.y, v.z, v.w};
            int e = 4 * i;
#pragma unroll
            for (int k = 0; k < 4; k++) {
                int ee = e + k;
                int j = ee / 3;
                int d = ee - 3 * j;
                if (d == 0)      bufA[0][j].x = vals[k];
                else if (d == 1) bufA[0][j].y = vals[k];
                else             bufA[1][j].x = vals[k];
            }
        }
    }
    __syncthreads();

    // ---- forward FFTs (2 packed signals) ----
    {
        float2 (*src)[1024] = bufA;
        float2 (*dst)[1024] = bufB;
#pragma unroll
        for (int s = 0; s < 10; s++) {
            const int L  = 1 << s;
            const int q  = t & (L - 1);
            const int d1 = ((t >> s) << (s + 1)) | q;
            const float2 w = tw[q << (9 - s)];
#pragma unroll
            for (int f = 0; f < 2; f++) {
                float2 a  = src[f][t];
                float2 bb = src[f][t + 512];
                float2 tb = make_float2(w.x * bb.x - w.y * bb.y,
                                        w.x * bb.y + w.y * bb.x);
                dst[f][d1]     = make_float2(a.x + tb.x, a.y + tb.y);
                dst[f][d1 + L] = make_float2(a.x - tb.x, a.y - tb.y);
            }
            float2 (*tmp)[1024] = src; src = dst; dst = tmp;
            __syncthreads();
        }
        // 10 stages (even) -> results back in bufA
    }

    // ---- power spectrum: u = P + 0i into bufB[0] ----
#pragma unroll
    for (int it = 0; it < 2; it++) {
        int k = t + it * 512;
        int m = (1024 - k) & 1023;
        float2 z  = bufA[0][k];
        float2 zm = bufA[0][m];
        float2 z2 = bufA[1][k];
        float P = 0.5f * (z.x * z.x + z.y * z.y + zm.x * zm.x + zm.y * zm.y)
                + (z2.x * z2.x + z2.y * z2.y);
        bufB[0][k] = make_float2(P, 0.0f);
    }
    __syncthreads();

    // ---- inverse (== forward on real-even P), single FFT ----
    {
        float2 (*src)[1024] = bufB;
        float2 (*dst)[1024] = bufA;
#pragma unroll
        for (int s = 0; s < 10; s++) {
            const int L  = 1 << s;
            const int q  = t & (L - 1);
            const int d1 = ((t >> s) << (s + 1)) | q;
            const float2 w = tw[q << (9 - s)];
            float2 a  = src[0][t];
            float2 bb = src[0][t + 512];
            float2 tb = make_float2(w.x * bb.x - w.y * bb.y,
                                    w.x * bb.y + w.y * bb.x);
            dst[0][d1]     = make_float2(a.x + tb.x, a.y + tb.y);
            dst[0][d1 + L] = make_float2(a.x - tb.x, a.y - tb.y);
            float2 (*tmp)[1024] = src; src = dst; dst = tmp;
            __syncthreads();
        }
        // results in bufB[0]
    }

    const float inv = 1.0f / (1024.0f * 1024.0f);
    g_c[(size_t)b * NSEQ + t]       = bufB[0][t].x * inv;
    g_c[(size_t)b * NSEQ + t + 512] = bufB[0][t + 512].x * inv;
}

// ---------------------------------------------------------------------------
// Kernel 2: tiled layer-1 GEMM, full K per block, writes FINAL h1 (w/ celu).
// Grid 128 = 16 batch-tiles (8 batches) x 8 h-tiles (16 h). 512 threads.
// ---------------------------------------------------------------------------
#define CSH_PITCH 1025
#define RED_PITCH 66
#define GEMM1_SMEM ((4 * CSH_PITCH + 1024 * 16 + 32 * RED_PITCH) * 8)

__global__ __launch_bounds__(512, 1)
void gemm1_kernel(const float* __restrict__ W1, const float* __restrict__ b1) {
    extern __shared__ char dsm[];
    u64 (*csh)[CSH_PITCH] = (u64(*)[CSH_PITCH])dsm;
    u64 (*w1d)[16]        = (u64(*)[16])(dsm + 4 * CSH_PITCH * 8);
    u64 (*red)[RED_PITCH] = (u64(*)[RED_PITCH])(dsm + (4 * CSH_PITCH + 1024 * 16) * 8);

    const int t  = threadIdx.x;
    const int bt = blockIdx.x >> 3;
    const int ht = blockIdx.x & 7;
    const int b0 = bt * 8;
    const int H0 = ht * 16;

#pragma unroll
    for (int it = 0; it < 8; it++) {
        int idx = t + it * 512;
        int bp_ = idx >> 10, j = idx & 1023;
        csh[bp_][j] = pk2(g_c[(b0 + 2 * bp_) * NSEQ + j],
                          g_c[(b0 + 2 * bp_ + 1) * NSEQ + j]);
    }
#pragma unroll
    for (int it = 0; it < 8; it++) {
        int idx = t + it * 512;
        int j = idx >> 2, hq = idx & 3;
        float4 wv = *(const float4*)&W1[j * HID + H0 + hq * 4];
        ulonglong2* dst = (ulonglong2*)&w1d[j][hq * 4];
        dst[0] = make_ulonglong2(pk2(wv.x, wv.x), pk2(wv.y, wv.y));
        dst[1] = make_ulonglong2(pk2(wv.z, wv.z), pk2(wv.w, wv.w));
    }
    __syncthreads();

    const int bp = t & 3;
    const int h4 = (t >> 2) & 3;
    const int jq = t >> 4;
    const int j0 = jq * 32;

    u64 a0 = 0ull, a1 = 0ull, a2 = 0ull, a3 = 0ull;
#pragma unroll 8
    for (int j = j0; j < j0 + 32; j++) {
        u64 cv = csh[bp][j];
        const ulonglong2* wr = (const ulonglong2*)&w1d[j][h4 * 4];
        ulonglong2 w01 = wr[0];
        ulonglong2 w23 = wr[1];
        a0 = fma2(cv, w01.x, a0);
        a1 = fma2(cv, w01.y, a1);
        a2 = fma2(cv, w23.x, a2);
        a3 = fma2(cv, w23.y, a3);
    }
    {
        ulonglong2* rr = (ulonglong2*)&red[jq][bp * 16 + h4 * 4];
        rr[0] = make_ulonglong2(a0, a1);
        rr[1] = make_ulonglong2(a2, a3);
    }
    __syncthreads();

    if (t < 64) {
        int bp_ = t >> 4, h = t & 15;
        int cell = bp_ * 16 + h;
        u64 s0 = 0ull, s1 = 0ull, s2 = 0ull, s3 = 0ull;
#pragma unroll
        for (int q = 0; q < 32; q += 4) {
            s0 = add2(s0, red[q + 0][cell]);
            s1 = add2(s1, red[q + 1][cell]);
            s2 = add2(s2, red[q + 2][cell]);
            s3 = add2(s3, red[q + 3][cell]);
        }
        u64 s = add2(add2(s0, s1), add2(s2, s3));
        float va, vb;
        upk2(s, va, vb);
        float bb = b1[H0 + h];
        g_h1[(b0 + 2 * bp_) * HID + H0 + h]     = celu1(va + bb);
        g_h1[(b0 + 2 * bp_ + 1) * HID + H0 + h] = celu1(vb + bb);
    }
}

// ---------------------------------------------------------------------------
// Kernel 3: layers 2+3. 128 blocks (one per batch), 256 threads (k split 2).
// ---------------------------------------------------------------------------
__global__ __launch_bounds__(256, 1)
void mlp23_kernel(const float* __restrict__ W2, const float* __restrict__ b2,
                  const float* __restrict__ W3, const float* __restrict__ b3,
                  float* __restrict__ out) {
    __shared__ float h1s[HID];
    __shared__ float s2[2][HID];

    const int b = blockIdx.x, t = threadIdx.x;
    if (t < HID) h1s[t] = g_h1[b * HID + t];
    __syncthreads();

    const int kh = t >> 7, h = t & (HID - 1);
    const int k0 = kh * 64;
    float acc0 = 0.f, acc1 = 0.f, acc2 = 0.f, acc3 = 0.f;
#pragma unroll
    for (int k = k0; k < k0 + 64; k += 4) {
        acc0 += h1s[k + 0] * W2[(k + 0) * HID + h];
        acc1 += h1s[k + 1] * W2[(k + 1) * HID + h];
        acc2 += h1s[k + 2] * W2[(k + 2) * HID + h];
        acc3 += h1s[k + 3] * W2[(k + 3) * HID + h];
    }
    s2[kh][h] = (acc0 + acc1) + (acc2 + acc3);
    __syncthreads();

    if (t < HID) {
        float v = s2[0][t] + s2[1][t] + b2[t];
        s2[0][t] = celu1(v) * W3[t];
    }
    __syncthreads();
#pragma unroll
    for (int o = 64; o > 0; o >>= 1) {
        if (t < o) s2[0][t] += s2[0][t + o];
        __syncthreads();
    }
    if (t == 0) out[b] = s2[0][0] + b3[0];
}

// ---------------------------------------------------------------------------
extern "C" void kernel_launch(void* const* d_in, const int* in_sizes, int n_in,
                              void* d_out, int out_size) {
    const float* x  = (const float*)d_in[0];
    const float* W1 = (const float*)d_in[1];
    const float* b1 = (const float*)d_in[2];
    const float* W2 = (const float*)d_in[3];
    const float* b2 = (const float*)d_in[4];
    const float* W3 = (const float*)d_in[5];
    const float* b3 = (const float*)d_in[6];
    float* out = (float*)d_out;

    cudaFuncSetAttribute(gemm1_kernel,
                         cudaFuncAttributeMaxDynamicSharedMemorySize, GEMM1_SMEM);

    fftcorr_kernel<<<BATCH, 512>>>(x);
    gemm1_kernel<<<128, 512, GEMM1_SMEM>>>(W1, b1);
    mlp23_kernel<<<BATCH, 256>>>(W2, b2, W3, b3, out);
}

// round 6
// speedup vs baseline: 2.3607x; 1.1215x over previous
#include <cuda_runtime.h>
#include <cuda_bf16.h>

// ---------------------------------------------------------------------------
// MLP_TI_Gram: y = MLP(mean-of-shifted-diagonal of per-batch Gram matrix)
// diag-mean == circular autocorrelation == FFT(sum_d |FFT(x_d)|^2)/N^2
// (Wiener-Khinchin; P real-even so inverse == forward FFT, real part).
// B=128, N=1024, H=128.
// Pipeline: fftcorr (radix-4) -> tiled gemm1 (final h1) -> mlp23.
// ---------------------------------------------------------------------------

#define BATCH 128
#define NSEQ  1024
#define HID   128

typedef unsigned long long u64;

__device__ float g_c[BATCH * NSEQ];    // correlation (scratch)
__device__ float g_h1[BATCH * HID];    // layer-1 activations (scratch)

// ---- f32x2 packed helpers (Blackwell, PTX-only) ---------------------------
__device__ __forceinline__ u64 pk2(float lo, float hi) {
    u64 r;
    asm("mov.b64 %0, {%1,%2};" : "=l"(r) : "f"(lo), "f"(hi));
    return r;
}
__device__ __forceinline__ void upk2(u64 v, float& lo, float& hi) {
    asm("mov.b64 {%0,%1}, %2;" : "=f"(lo), "=f"(hi) : "l"(v));
}
__device__ __forceinline__ u64 fma2(u64 a, u64 b, u64 c) {
    u64 d;
    asm("fma.rn.f32x2 %0, %1, %2, %3;" : "=l"(d) : "l"(a), "l"(b), "l"(c));
    return d;
}
__device__ __forceinline__ u64 add2(u64 a, u64 b) {
    u64 d;
    asm("add.rn.f32x2 %0, %1, %2;" : "=l"(d) : "l"(a), "l"(b));
    return d;
}

__device__ __forceinline__ float celu1(float v) {
    return v > 0.0f ? v : expm1f(v);
}

__device__ __forceinline__ float2 cmul(float2 a, float2 b) {
    return make_float2(a.x * b.x - a.y * b.y, a.x * b.y + a.y * b.x);
}

// ---------------------------------------------------------------------------
// Kernel 1: correlation via FFT (Wiener-Khinchin), radix-4 Stockham.
// 128 blocks (one per batch), 512 threads.
// Forward: 2 complex 1024-pt FFTs (ch0 + i*ch1 packed, ch2 + 0i), 5 stages.
// P[k] = 0.5*(|Z01[k]|^2 + |Z01[N-k]|^2) + |Z2[k]|^2
// c[r] = Re(FFT(P))[r] / N^2  (P real-even -> forward == inverse up to scale).
// ---------------------------------------------------------------------------
__global__ __launch_bounds__(512, 1)
void fftcorr_kernel(const float* __restrict__ x) {
    __shared__ float2 bufA[2][1024];   // 16KB
    __shared__ float2 bufB[2][1024];   // 16KB
    __shared__ float2 tw[512];         // W_1024^m, m in [0,512)

    const int b = blockIdx.x;
    const int t = threadIdx.x;

    // twiddle: tw[m] = exp(-2*pi*i*m/1024)
    {
        float s_, c_;
        sincospif(-(float)t * (1.0f / 512.0f), &s_, &c_);
        tw[t] = make_float2(c_, s_);
    }
    // zero imag of channel-2 signal
    bufA[1][t].y = 0.0f;
    bufA[1][t + 512].y = 0.0f;

    // load x[b]: 3072 floats = 768 float4, scatter to (j, d)
    {
        const float4* __restrict__ xv = (const float4*)(x + (size_t)b * NSEQ * 3);
        for (int i = t; i < 768; i += 512) {
            float4 v = xv[i];
            float vals[4] = {v.x, v.y, v.z, v.w};
            int e = 4 * i;
#pragma unroll
            for (int k = 0; k < 4; k++) {
                int ee = e + k;
                int j = ee / 3;
                int d = ee - 3 * j;
                if (d == 0)      bufA[0][j].x = vals[k];
                else if (d == 1) bufA[0][j].y = vals[k];
                else             bufA[1][j].x = vals[k];
            }
        }
    }
    __syncthreads();

    const int f = t >> 8;       // signal (0: ch0+i*ch1, 1: ch2)
    const int i = t & 255;      // butterfly index

    // ---- forward: 5 radix-4 stages, both signals ----
    {
        float2 (*src)[1024] = bufA;
        float2 (*dst)[1024] = bufB;
#pragma unroll
        for (int s = 0; s < 5; s++) {
            const int L = 1 << (2 * s);
            const int q = i & (L - 1);
            const int d = ((i >> (2 * s)) << (2 * s + 2)) | q;
            const float2 w1 = tw[q << (8 - 2 * s)];
            const float2 w2 = make_float2(w1.x * w1.x - w1.y * w1.y,
                                          2.0f * w1.x * w1.y);
            const float2 w3 = cmul(w2, w1);

            float2 a0 = src[f][i];
            float2 a1 = src[f][i + 256];
            float2 a2 = src[f][i + 512];
            float2 a3 = src[f][i + 768];
            float2 b1 = cmul(a1, w1);
            float2 b2 = cmul(a2, w2);
            float2 b3 = cmul(a3, w3);

            float2 t02p = make_float2(a0.x + b2.x, a0.y + b2.y);
            float2 t02m = make_float2(a0.x - b2.x, a0.y - b2.y);
            float2 t13p = make_float2(b1.x + b3.x, b1.y + b3.y);
            float2 t13m = make_float2(b1.x - b3.x, b1.y - b3.y);

            dst[f][d]         = make_float2(t02p.x + t13p.x, t02p.y + t13p.y);
            dst[f][d + L]     = make_float2(t02m.x + t13m.y, t02m.y - t13m.x);
            dst[f][d + 2 * L] = make_float2(t02p.x - t13p.x, t02p.y - t13p.y);
            dst[f][d + 3 * L] = make_float2(t02m.x - t13m.y, t02m.y + t13m.x);

            float2 (*tmp)[1024] = src; src = dst; dst = tmp;
            __syncthreads();
        }
        // 5 stages (odd) -> spectra in bufB
    }

    // ---- power spectrum: P + 0i into bufA[0] ----
#pragma unroll
    for (int it = 0; it < 2; it++) {
        int k = t + it * 512;
        int m = (1024 - k) & 1023;
        float2 z  = bufB[0][k];
        float2 zm = bufB[0][m];
        float2 z2 = bufB[1][k];
        float P = 0.5f * (z.x * z.x + z.y * z.y + zm.x * zm.x + zm.y * zm.y)
                + (z2.x * z2.x + z2.y * z2.y);
        bufA[0][k] = make_float2(P, 0.0f);
    }
    __syncthreads();

    // ---- inverse (== forward on real-even P): 5 radix-4 stages, 1 signal ----
    {
        float2 (*src)[1024] = bufA;
        float2 (*dst)[1024] = bufB;
#pragma unroll
        for (int s = 0; s < 5; s++) {
            if (t < 256) {
                const int L = 1 << (2 * s);
                const int q = t & (L - 1);
                const int d = ((t >> (2 * s)) << (2 * s + 2)) | q;
                const float2 w1 = tw[q << (8 - 2 * s)];
                const float2 w2 = make_float2(w1.x * w1.x - w1.y * w1.y,
                                              2.0f * w1.x * w1.y);
                const float2 w3 = cmul(w2, w1);

                float2 a0 = src[0][t];
                float2 a1 = src[0][t + 256];
                float2 a2 = src[0][t + 512];
                float2 a3 = src[0][t + 768];
                float2 b1 = cmul(a1, w1);
                float2 b2 = cmul(a2, w2);
                float2 b3 = cmul(a3, w3);

                float2 t02p = make_float2(a0.x + b2.x, a0.y + b2.y);
                float2 t02m = make_float2(a0.x - b2.x, a0.y - b2.y);
                float2 t13p = make_float2(b1.x + b3.x, b1.y + b3.y);
                float2 t13m = make_float2(b1.x - b3.x, b1.y - b3.y);

                dst[0][d]         = make_float2(t02p.x + t13p.x, t02p.y + t13p.y);
                dst[0][d + L]     = make_float2(t02m.x + t13m.y, t02m.y - t13m.x);
                dst[0][d + 2 * L] = make_float2(t02p.x - t13p.x, t02p.y - t13p.y);
                dst[0][d + 3 * L] = make_float2(t02m.x - t13m.y, t02m.y + t13m.x);
            }
            float2 (*tmp)[1024] = src; src = dst; dst = tmp;
            __syncthreads();
        }
        // result in bufB[0]
    }

    const float inv = 1.0f / (1024.0f * 1024.0f);
    g_c[(size_t)b * NSEQ + t]       = bufB[0][t].x * inv;
    g_c[(size_t)b * NSEQ + t + 512] = bufB[0][t + 512].x * inv;
}

// ---------------------------------------------------------------------------
// Kernel 2: tiled layer-1 GEMM, full K per block, writes FINAL h1 (w/ celu).
// Grid 128 = 16 batch-tiles (8 batches) x 8 h-tiles (16 h). 512 threads.
// ---------------------------------------------------------------------------
#define CSH_PITCH 1025
#define RED_PITCH 66
#define GEMM1_SMEM ((4 * CSH_PITCH + 1024 * 16 + 32 * RED_PITCH) * 8)

__global__ __launch_bounds__(512, 1)
void gemm1_kernel(const float* __restrict__ W1, const float* __restrict__ b1) {
    extern __shared__ char dsm[];
    u64 (*csh)[CSH_PITCH] = (u64(*)[CSH_PITCH])dsm;
    u64 (*w1d)[16]        = (u64(*)[16])(dsm + 4 * CSH_PITCH * 8);
    u64 (*red)[RED_PITCH] = (u64(*)[RED_PITCH])(dsm + (4 * CSH_PITCH + 1024 * 16) * 8);

    const int t  = threadIdx.x;
    const int bt = blockIdx.x >> 3;
    const int ht = blockIdx.x & 7;
    const int b0 = bt * 8;
    const int H0 = ht * 16;

#pragma unroll
    for (int it = 0; it < 8; it++) {
        int idx = t + it * 512;
        int bp_ = idx >> 10, j = idx & 1023;
        csh[bp_][j] = pk2(g_c[(b0 + 2 * bp_) * NSEQ + j],
                          g_c[(b0 + 2 * bp_ + 1) * NSEQ + j]);
    }
#pragma unroll
    for (int it = 0; it < 8; it++) {
        int idx = t + it * 512;
        int j = idx >> 2, hq = idx & 3;
        float4 wv = *(const float4*)&W1[j * HID + H0 + hq * 4];
        ulonglong2* dst = (ulonglong2*)&w1d[j][hq * 4];
        dst[0] = make_ulonglong2(pk2(wv.x, wv.x), pk2(wv.y, wv.y));
        dst[1] = make_ulonglong2(pk2(wv.z, wv.z), pk2(wv.w, wv.w));
    }
    __syncthreads();

    const int bp = t & 3;
    const int h4 = (t >> 2) & 3;
    const int jq = t >> 4;
    const int j0 = jq * 32;

    u64 a0 = 0ull, a1 = 0ull, a2 = 0ull, a3 = 0ull;
#pragma unroll 8
    for (int j = j0; j < j0 + 32; j++) {
        u64 cv = csh[bp][j];
        const ulonglong2* wr = (const ulonglong2*)&w1d[j][h4 * 4];
        ulonglong2 w01 = wr[0];
        ulonglong2 w23 = wr[1];
        a0 = fma2(cv, w01.x, a0);
        a1 = fma2(cv, w01.y, a1);
        a2 = fma2(cv, w23.x, a2);
        a3 = fma2(cv, w23.y, a3);
    }
    {
        ulonglong2* rr = (ulonglong2*)&red[jq][bp * 16 + h4 * 4];
        rr[0] = make_ulonglong2(a0, a1);
        rr[1] = make_ulonglong2(a2, a3);
    }
    __syncthreads();

    if (t < 64) {
        int bp_ = t >> 4, h = t & 15;
        int cell = bp_ * 16 + h;
        u64 s0 = 0ull, s1 = 0ull, s2 = 0ull, s3 = 0ull;
#pragma unroll
        for (int q = 0; q < 32; q += 4) {
            s0 = add2(s0, red[q + 0][cell]);
            s1 = add2(s1, red[q + 1][cell]);
            s2 = add2(s2, red[q + 2][cell]);
            s3 = add2(s3, red[q + 3][cell]);
        }
        u64 s = add2(add2(s0, s1), add2(s2, s3));
        float va, vb;
        upk2(s, va, vb);
        float bb = b1[H0 + h];
        g_h1[(b0 + 2 * bp_) * HID + H0 + h]     = celu1(va + bb);
        g_h1[(b0 + 2 * bp_ + 1) * HID + H0 + h] = celu1(vb + bb);
    }
}

// ---------------------------------------------------------------------------
// Kernel 3: layers 2+3. 128 blocks (one per batch), 256 threads (k split 2).
// ---------------------------------------------------------------------------
__global__ __launch_bounds__(256, 1)
void mlp23_kernel(const float* __restrict__ W2, const float* __restrict__ b2,
                  const float* __restrict__ W3, const float* __restrict__ b3,
                  float* __restrict__ out) {
    __shared__ float h1s[HID];
    __shared__ float s2[2][HID];

    const int b = blockIdx.x, t = threadIdx.x;
    if (t < HID) h1s[t] = g_h1[b * HID + t];
    __syncthreads();

    const int kh = t >> 7, h = t & (HID - 1);
    const int k0 = kh * 64;
    float acc0 = 0.f, acc1 = 0.f, acc2 = 0.f, acc3 = 0.f;
#pragma unroll
    for (int k = k0; k < k0 + 64; k += 4) {
        acc0 += h1s[k + 0] * W2[(k + 0) * HID + h];
        acc1 += h1s[k + 1] * W2[(k + 1) * HID + h];
        acc2 += h1s[k + 2] * W2[(k + 2) * HID + h];
        acc3 += h1s[k + 3] * W2[(k + 3) * HID + h];
    }
    s2[kh][h] = (acc0 + acc1) + (acc2 + acc3);
    __syncthreads();

    if (t < HID) {
        float v = s2[0][t] + s2[1][t] + b2[t];
        s2[0][t] = celu1(v) * W3[t];
    }
    __syncthreads();
#pragma unroll
    for (int o = 64; o > 0; o >>= 1) {
        if (t < o) s2[0][t] += s2[0][t + o];
        __syncthreads();
    }
    if (t == 0) out[b] = s2[0][0] + b3[0];
}

// ---------------------------------------------------------------------------
extern "C" void kernel_launch(void* const* d_in, const int* in_sizes, int n_in,
                              void* d_out, int out_size) {
    const float* x  = (const float*)d_in[0];
    const float* W1 = (const float*)d_in[1];
    const float* b1 = (const float*)d_in[2];
    const float* W2 = (const float*)d_in[3];
    const float* b2 = (const float*)d_in[4];
    const float* W3 = (const float*)d_in[5];
    const float* b3 = (const float*)d_in[6];
    float* out = (float*)d_out;

    cudaFuncSetAttribute(gemm1_kernel,
                         cudaFuncAttributeMaxDynamicSharedMemorySize, GEMM1_SMEM);

    fftcorr_kernel<<<BATCH, 512>>>(x);
    gemm1_kernel<<<128, 512, GEMM1_SMEM>>>(W1, b1);
    mlp23_kernel<<<BATCH, 256>>>(W2, b2, W3, b3, out);
}